// round 5
// baseline (speedup 1.0000x reference)
#include <cuda_runtime.h>
#include <cstdint>

typedef unsigned long long ull;

#define NNODES 20000
#define NEDGES 640000
#define IND    256
#define HID    128
#define NG     64

#define NB     136          // nodes per CTA
#define KBLK   148          // ceil(20000/136), one CTA per SM
#define STG    8            // nodes per stage
#define NSTAGE 17           // stages per CTA
#define DEPTH  3            // cp.async pipeline depth

// ---------------- device scratch ----------------
__device__ int   g_C[NNODES * NG];          // [node][graph] dst counts
__device__ int   g_outdeg[NNODES];
__device__ int   g_cnt[NG];
__device__ int   g_firstg[KBLK];            // first graph id in each CTA's window
__device__ float g_xdpart[KBLK][NG][IND];   // dst-pool split-K partials (9.7 MB)
__device__ float g_xs4[KBLK][4][IND];       // src-pool slot partials (0.6 MB)
__device__ float g_XF[128][IND];            // rows 0..63 src-pool, 64..127 dst-pool
__device__ float g_P[2][128][HID];          // layer activations

// ---------------- helpers ----------------
__device__ __forceinline__ ull fma2(ull a, ull b, ull c) {
    ull d;
    asm("fma.rn.f32x2 %0, %1, %2, %3;" : "=l"(d) : "l"(a), "l"(b), "l"(c));
    return d;
}
__device__ __forceinline__ uint32_t smem_u32(const void* p) {
    uint32_t a;
    asm("{ .reg .u64 t; cvta.to.shared.u64 t, %1; cvt.u32.u64 %0, t; }" : "=r"(a) : "l"(p));
    return a;
}
// 16B async copy; pred=false -> zero-fill (src-size 0), no OOB read
__device__ __forceinline__ void cpa16(uint32_t dst, const float* src, bool pred) {
    int sz = pred ? 16 : 0;
    asm volatile("cp.async.cg.shared.global [%0], [%1], 16, %2;"
                 :: "r"(dst), "l"(src), "r"(sz) : "memory");
}
#define CP_COMMIT() asm volatile("cp.async.commit_group;" ::: "memory")
#define CP_WAIT2()  asm volatile("cp.async.wait_group 2;" ::: "memory")

// ---------------- kernels ----------------
__global__ void zero_k() {
    int i = blockIdx.x * blockDim.x + threadIdx.x;
    int4 z = make_int4(0, 0, 0, 0);
    if (i < NNODES * NG / 4) ((int4*)g_C)[i] = z;
    if (i < NNODES / 4)      ((int4*)g_outdeg)[i] = z;
    if (i < NG / 4)          ((int4*)g_cnt)[i] = z;
}

__global__ void count_k(const int* __restrict__ src, const int* __restrict__ dst,
                        const int* __restrict__ batch) {
    __shared__ int hist[NG];
    int t = threadIdx.x;
    if (t < NG) hist[t] = 0;
    __syncthreads();
    int e = blockIdx.x * blockDim.x + t;
    if (e < NEDGES) {
        int s = src[e];
        int d = dst[e];
        int g = batch[s];
        atomicAdd(&g_C[d * NG + g], 1);
        atomicAdd(&g_outdeg[s], 1);
        atomicAdd(&hist[g], 1);
    }
    __syncthreads();
    if (t < NG && hist[t]) atomicAdd(&g_cnt[t], hist[t]);
}

// Fused pooling GEMM:
//   dst rows: XDpart[b][g][f] = sum_{n in window} C[n][g] * x[n][f]
//   src rows: XS4[b][slot][f] = sum_{n: batch[n]==firstg+slot} outdeg[n] * x[n][f]
// 512 threads: 8 row-groups x 8 rows, 64 col-groups x 4 cols.
// x staged via 3-deep cp.async; C/outdeg staged via 1-ahead register prefetch.
__global__ void __launch_bounds__(512, 1) pool_mm(const float* __restrict__ x,
                                                  const int* __restrict__ batch) {
    __shared__ float  xs[DEPTH][STG * IND];   // 24 KB
    __shared__ float2 cs[DEPTH][STG * NG];    // 12 KB (duplicated counts)
    __shared__ float2 ws[DEPTH][STG * 4];     // 768 B (slot weights, duplicated)

    int b   = blockIdx.x;
    int n0  = b * NB;
    int tid = threadIdx.x;
    int rg  = tid >> 6;     // row group 0..7 -> rows rg*8..+7 ; slot rg&3
    int co  = tid & 63;     // cols co*4..+3
    int ni  = tid >> 6;     // staging: node in stage
    int gc  = tid & 63;     // staging: graph / float4 col
    int firstg = batch[n0];
    uint32_t xs_b = smem_u32(xs);

    ull accd[8][2];
    ull acs0 = 0, acs1 = 0;
#pragma unroll
    for (int i = 0; i < 8; i++) { accd[i][0] = 0; accd[i][1] = 0; }

    // stage 0 C/w direct
    {
        int n = n0 + ni;
        float c = (n < NNODES) ? (float)g_C[n * NG + gc] : 0.f;
        cs[0][tid] = make_float2(c, c);
        if (tid < STG) {
            int n2 = n0 + tid;
            float w = 0.f; int sl = -1;
            if (n2 < NNODES) { w = (float)g_outdeg[n2]; sl = batch[n2] - firstg; }
#pragma unroll
            for (int s4 = 0; s4 < 4; s4++)
                ws[0][tid * 4 + s4] = (s4 == sl) ? make_float2(w, w) : make_float2(0.f, 0.f);
        }
    }
    // x async stages 0..2
#pragma unroll
    for (int p = 0; p < DEPTH; p++) {
        int n = n0 + p * STG + ni;
        cpa16(xs_b + (uint32_t)(p * STG * IND + tid * 4) * 4,
              x + (size_t)n * IND + gc * 4, n < NNODES);
        CP_COMMIT();
    }
    // register prefetch for stage 1
    int crN = 0; float wN = 0.f; int slN = -1;
    {
        int n = n0 + STG + ni;
        if (n < NNODES) crN = g_C[n * NG + gc];
        if (tid < STG) {
            int n2 = n0 + STG + tid;
            if (n2 < NNODES) { wN = (float)g_outdeg[n2]; slN = batch[n2] - firstg; }
        }
    }

    for (int s = 0; s < NSTAGE; s++) {
        int buf = s % 3;
        CP_WAIT2();
        __syncthreads();
#pragma unroll
        for (int kk = 0; kk < STG; kk++) {
            ulonglong2 xv = *(ulonglong2*)&xs[buf][kk * IND + co * 4];   // 4 cols
            const float2* cb = &cs[buf][kk * NG + rg * 8];               // 8 dup'd rows
            ulonglong2 c01 = *(ulonglong2*)&cb[0];
            ulonglong2 c23 = *(ulonglong2*)&cb[2];
            ulonglong2 c45 = *(ulonglong2*)&cb[4];
            ulonglong2 c67 = *(ulonglong2*)&cb[6];
            ull cd[8] = {c01.x, c01.y, c23.x, c23.y, c45.x, c45.y, c67.x, c67.y};
            ull wv = *(ull*)&ws[buf][kk * 4 + (rg & 3)];
#pragma unroll
            for (int i = 0; i < 8; i++) {
                accd[i][0] = fma2(cd[i], xv.x, accd[i][0]);
                accd[i][1] = fma2(cd[i], xv.y, accd[i][1]);
            }
            acs0 = fma2(wv, xv.x, acs0);
            acs1 = fma2(wv, xv.y, acs1);
        }
        __syncthreads();
        // store stage s+1 C/w from regs into its buffer (free since stage s-2 done)
        if (s + 1 < NSTAGE) {
            int nbuf = (s + 1) % 3;
            float c = (float)crN;
            cs[nbuf][tid] = make_float2(c, c);
            if (tid < STG) {
#pragma unroll
                for (int s4 = 0; s4 < 4; s4++)
                    ws[nbuf][tid * 4 + s4] = (s4 == slN) ? make_float2(wN, wN)
                                                         : make_float2(0.f, 0.f);
            }
        }
        // issue x for stage s+3 into buffer (s%3)
        {
            int p = s + DEPTH;
            if (p < NSTAGE) {
                int n = n0 + p * STG + ni;
                cpa16(xs_b + (uint32_t)(buf * STG * IND + tid * 4) * 4,
                      x + (size_t)n * IND + gc * 4, n < NNODES);
            }
            CP_COMMIT();   // commit even when empty to keep group counts aligned
        }
        // register prefetch stage s+2 C/w
        {
            int p = s + 2;
            crN = 0; wN = 0.f; slN = -1;
            if (p < NSTAGE) {
                int n = n0 + p * STG + ni;
                if (n < NNODES) crN = g_C[n * NG + gc];
                if (tid < STG) {
                    int n2 = n0 + p * STG + tid;
                    if (n2 < NNODES) { wN = (float)g_outdeg[n2]; slN = batch[n2] - firstg; }
                }
            }
        }
    }

    // epilogue: write partials
#pragma unroll
    for (int i = 0; i < 8; i++) {
        int r = rg * 8 + i;
        ulonglong2 v; v.x = accd[i][0]; v.y = accd[i][1];
        *(ulonglong2*)&g_xdpart[b][r][co * 4] = v;
    }
    if (rg < 4) {
        ulonglong2 v; v.x = acs0; v.y = acs1;
        *(ulonglong2*)&g_xs4[b][rg][co * 4] = v;
    }
    if (tid == 0) g_firstg[b] = firstg;
}

// fold partials + normalize. XF rows: 0..63 src-pool, 64..127 dst-pool.
__global__ void reduce_k() {
    int m = blockIdx.x;    // 0..127
    int f = threadIdx.x;   // 0..255
    int g = (m < NG) ? m : (m - NG);
    int cnt = g_cnt[g];
    float inv = cnt > 0 ? 1.0f / (float)cnt : 0.0f;
    float acc = 0.f;
    if (m >= NG) {
        float a[4] = {0.f, 0.f, 0.f, 0.f};
        for (int bq = 0; bq < KBLK; bq += 4) {
            a[0] += g_xdpart[bq + 0][g][f];
            a[1] += g_xdpart[bq + 1][g][f];
            a[2] += g_xdpart[bq + 2][g][f];
            a[3] += g_xdpart[bq + 3][g][f];
        }
        acc = (a[0] + a[1]) + (a[2] + a[3]);
    } else {
        for (int bq = 0; bq < KBLK; bq++) {
            int sl = g - g_firstg[bq];
            if (sl >= 0 && sl < 4) acc += g_xs4[bq][sl][f];
        }
    }
    g_XF[m][f] = acc * inv;
}

// one affine layer: P = (A @ W + b) * flag ; scatter into output
__global__ void head_k(const float* __restrict__ A, int K,
                       const float* __restrict__ W, const float* __restrict__ bias,
                       float* __restrict__ Pout, float* __restrict__ out, int layer) {
    __shared__ float As[16][17];
    __shared__ float Ws[16][17];
    int r0 = blockIdx.y * 16;
    int c0 = blockIdx.x * 16;
    int ty = threadIdx.y, tx = threadIdx.x;
    float acc = 0.f;
    for (int k0 = 0; k0 < K; k0 += 16) {
        As[ty][tx] = A[(r0 + ty) * K + k0 + tx];
        Ws[ty][tx] = W[(k0 + ty) * HID + c0 + tx];
        __syncthreads();
#pragma unroll
        for (int kk = 0; kk < 16; kk++) acc += As[ty][kk] * Ws[kk][tx];
        __syncthreads();
    }
    int r = r0 + ty, c = c0 + tx;
    int g = r & (NG - 1);
    float flag = g_cnt[g] > 0 ? 1.0f : 0.0f;
    float v = (acc + bias[c]) * flag;
    if (Pout) Pout[r * HID + c] = v;
    int col = layer * 256 + ((r < NG) ? 0 : HID) + c;
    out[g * 768 + col] = v;
}

// ---------------- launcher ----------------
extern "C" void kernel_launch(void* const* d_in, const int* in_sizes, int n_in,
                              void* d_out, int out_size) {
    const float* x     = (const float*)d_in[0];
    const int*   eidx  = (const int*)d_in[1];
    const int*   batch = (const int*)d_in[2];
    const float* W0 = (const float*)d_in[3];
    const float* b0 = (const float*)d_in[4];
    const float* W1 = (const float*)d_in[5];
    const float* b1 = (const float*)d_in[6];
    const float* W2 = (const float*)d_in[7];
    const float* b2 = (const float*)d_in[8];
    float* out = (float*)d_out;

    const int* src = eidx;
    const int* dst = eidx + NEDGES;

    zero_k<<<(NNODES * NG / 4 + 255) / 256, 256>>>();
    count_k<<<NEDGES / 256, 256>>>(src, dst, batch);
    pool_mm<<<KBLK, 512>>>(x, batch);
    reduce_k<<<128, IND>>>();

    float *P0, *P1;
    cudaGetSymbolAddress((void**)&P0, g_P);
    P1 = P0 + 128 * HID;
    float* XF;
    cudaGetSymbolAddress((void**)&XF, g_XF);

    dim3 hb(16, 16), hg(HID / 16, 128 / 16);
    head_k<<<hg, hb>>>(XF, IND, W0, b0, P0, out, 0);
    head_k<<<hg, hb>>>(P0, HID, W1, b1, P1, out, 1);
    head_k<<<hg, hb>>>(P1, HID, W2, b2, nullptr, out, 2);
}

// round 7
// speedup vs baseline: 1.1605x; 1.1605x over previous
#include <cuda_runtime.h>
#include <cuda_bf16.h>
#include <cstdint>

#define NNODES 20000
#define NEDGES 640000
#define IND    256
#define HID    128
#define NG     64

#define KBLK   139          // CTAs in split-K
#define NB     144          // nodes per CTA
#define NST    9            // stages of 16 nodes
#define RGRP   5            // reduce1 groups
#define RSPAN  28           // partials per reduce1 group

// ---------------- device scratch ----------------
__device__ __align__(16) unsigned g_Cp[NNODES * 16];      // packed u8 counts [node][g], 1.25 MB
__device__ __align__(16) int      g_outdeg[NNODES];
__device__ __align__(16) int      g_cnt[NG];
__device__ __align__(16) float    g_part[KBLK][128][IND]; // split-K partials (18.2 MB)
__device__ __align__(16) float    g_r1[RGRP][128][IND];   // reduce1 partials
__device__ __align__(16) float    g_XF[128][IND];         // rows 0..63 src-pool, 64..127 dst-pool
__device__ __align__(16) float    g_P[2][128][HID];       // layer activations

// ---------------- helpers ----------------
__device__ __forceinline__ uint32_t smem_u32(const void* p) {
    uint32_t a;
    asm("{ .reg .u64 t; cvta.to.shared.u64 t, %1; cvt.u32.u64 %0, t; }" : "=r"(a) : "l"(p));
    return a;
}
__device__ __forceinline__ void mma16816(float* d, uint32_t a0, uint32_t a1, uint32_t a2,
                                         uint32_t a3, uint32_t b0, uint32_t b1) {
    asm volatile(
        "mma.sync.aligned.m16n8k16.row.col.f32.bf16.bf16.f32 "
        "{%0,%1,%2,%3},{%4,%5,%6,%7},{%8,%9},{%0,%1,%2,%3};"
        : "+f"(d[0]), "+f"(d[1]), "+f"(d[2]), "+f"(d[3])
        : "r"(a0), "r"(a1), "r"(a2), "r"(a3), "r"(b0), "r"(b1));
}
__device__ __forceinline__ void ldsm4t(uint32_t& r0, uint32_t& r1, uint32_t& r2,
                                       uint32_t& r3, uint32_t addr) {
    asm volatile("ldmatrix.sync.aligned.m8n8.x4.trans.shared.b16 {%0,%1,%2,%3}, [%4];"
                 : "=r"(r0), "=r"(r1), "=r"(r2), "=r"(r3) : "r"(addr));
}
__device__ __forceinline__ uint32_t packbf2(float a, float b) {
    __nv_bfloat162 h = __floats2bfloat162_rn(a, b);
    return *(uint32_t*)&h;
}

// ---------------- kernels ----------------
__global__ void zero_k() {
    int i = blockIdx.x * blockDim.x + threadIdx.x;
    uint4 zu = make_uint4(0u, 0u, 0u, 0u);
    int4  zi = make_int4(0, 0, 0, 0);
    if (i < NNODES * 16 / 4) ((uint4*)g_Cp)[i] = zu;
    if (i < NNODES / 4)      ((int4*)g_outdeg)[i] = zi;
    if (i < NG / 4)          ((int4*)g_cnt)[i] = zi;
}

__global__ void count_k(const int* __restrict__ src, const int* __restrict__ dst,
                        const int* __restrict__ batch) {
    __shared__ int hist[NG];
    int t = threadIdx.x;
    if (t < NG) hist[t] = 0;
    __syncthreads();
    int e = blockIdx.x * blockDim.x + t;
    if (e < NEDGES) {
        int s = src[e];
        int d = dst[e];
        int g = batch[s];
        atomicAdd(&g_Cp[d * 16 + (g >> 2)], 1u << ((g & 3) * 8));
        atomicAdd(&g_outdeg[s], 1);
        atomicAdd(&hist[g], 1);
    }
    __syncthreads();
    if (t < NG && hist[t]) atomicAdd(&g_cnt[t], hist[t]);
}

// Tensor-core pooling GEMM: part[b] = A[128][16nodes...] @ x(nodes)[256]
//   A rows 0-63: dst counts C[g][n];  rows 64-127: outdeg[n] * [batch[n]==g]
// x split to bf16 hi+lo in-kernel. 512 thr, 16 warps (wm=warp&7 m-tile, wn=warp>>3 n-half).
__global__ void __launch_bounds__(512, 1) mm_k(const float* __restrict__ x,
                                               const int* __restrict__ batch) {
    __shared__ __align__(16) __nv_bfloat16 Asm[2][128 * 16]; // [m][k], 32B rows
    __shared__ __align__(16) __nv_bfloat16 Bh[2][16 * 256];  // [k][n] swizzled
    __shared__ __align__(16) __nv_bfloat16 Bl[2][16 * 256];

    const uint8_t* C8 = (const uint8_t*)g_Cp;
    int b    = blockIdx.x;
    int n0   = b * NB;
    int tid  = threadIdx.x;
    int lane = tid & 31;
    int warp = tid >> 5;
    int wm   = warp & 7;
    int wn   = warp >> 3;

    // staging roles
    int kx = warp;          // x-staging: node-in-stage = warp id (0..15)
    int cx = lane;          // 16B block (8 features)
    int ma = tid & 127;     // A-staging row
    int kh = tid >> 7;      // A-staging k quarter (0..3)

    float acc[16][4];
#pragma unroll
    for (int i = 0; i < 16; i++)
#pragma unroll
        for (int j = 0; j < 4; j++) acc[i][j] = 0.f;

    const float4* x4 = (const float4*)x;

    // ldmatrix per-lane address components
    int lr   = lane & 7;
    int seg  = lane >> 3;
    int krow = (seg & 1) * 8 + lr;
    int cseg = seg >> 1;                 // +0 / +1 16B-block (n+8)
    int krow512 = krow * 512;
    int kmask   = krow & 7;

    // ---- prefetch (register, one stage ahead) ----
    float4 pv0, pv1;
    float  pa[4];
    auto prefetch = [&](int s) {
        int nx = n0 + s * 16 + kx;
        if (nx < NNODES) {
            pv0 = x4[(size_t)nx * 64 + cx * 2];
            pv1 = x4[(size_t)nx * 64 + cx * 2 + 1];
        } else {
            pv0 = make_float4(0.f, 0.f, 0.f, 0.f);
            pv1 = pv0;
        }
#pragma unroll
        for (int j = 0; j < 4; j++) {
            int na = n0 + s * 16 + kh * 4 + j;
            float v = 0.f;
            if (na < NNODES) {
                if (ma < NG) {
                    v = (float)C8[na * 64 + ma];
                } else {
                    int g = ma - NG;
                    if (batch[na] == g) v = (float)g_outdeg[na];
                }
            }
            pa[j] = v;
        }
    };
    auto stage = [&](int buf) {
        // x: hi/lo split, swizzled 16B blocks
        uint32_t hblk[4], lblk[4];
        float vs[8] = {pv0.x, pv0.y, pv0.z, pv0.w, pv1.x, pv1.y, pv1.z, pv1.w};
        float hs[8], ls[8];
#pragma unroll
        for (int q = 0; q < 8; q++) {
            hs[q] = __bfloat162float(__float2bfloat16_rn(vs[q]));
            ls[q] = vs[q] - hs[q];
        }
#pragma unroll
        for (int q = 0; q < 4; q++) {
            hblk[q] = packbf2(hs[q * 2], hs[q * 2 + 1]);
            lblk[q] = packbf2(ls[q * 2], ls[q * 2 + 1]);
        }
        uint32_t off = (uint32_t)kx * 512 + (uint32_t)((cx ^ (kx & 7)) << 4);
        *(uint4*)((char*)Bh[buf] + off) = *(uint4*)hblk;
        *(uint4*)((char*)Bl[buf] + off) = *(uint4*)lblk;
        // A: 4 bf16 contiguous in k
        uint32_t aw[2];
        aw[0] = packbf2(pa[0], pa[1]);
        aw[1] = packbf2(pa[2], pa[3]);
        *(uint2*)&Asm[buf][ma * 16 + kh * 4] = *(uint2*)aw;
    };

    prefetch(0);
    stage(0);

    for (int s = 0; s < NST; s++) {
        __syncthreads();
        int buf = s & 1;
        if (s + 1 < NST) prefetch(s + 1);

        // A fragments (m16 k16 tile of this warp)
        const uint32_t* A32 = (const uint32_t*)Asm[buf];
        int ai = (wm * 16 + (lane >> 2)) * 8 + (lane & 3);
        uint32_t a0 = A32[ai];
        uint32_t a1 = A32[ai + 64];
        uint32_t a2 = A32[ai + 4];
        uint32_t a3 = A32[ai + 68];

        uint32_t bh_base = smem_u32(Bh[buf]);
        uint32_t bl_base = smem_u32(Bl[buf]);
#pragma unroll
        for (int nb2 = 0; nb2 < 8; nb2++) {
            int nblk = wn * 16 + nb2 * 2 + cseg;
            uint32_t off = (uint32_t)krow512 + (uint32_t)((nblk ^ kmask) << 4);
            uint32_t b0, b1, b2, b3;
            ldsm4t(b0, b1, b2, b3, bh_base + off);
            mma16816(acc[nb2 * 2],     a0, a1, a2, a3, b0, b1);
            mma16816(acc[nb2 * 2 + 1], a0, a1, a2, a3, b2, b3);
            ldsm4t(b0, b1, b2, b3, bl_base + off);
            mma16816(acc[nb2 * 2],     a0, a1, a2, a3, b0, b1);
            mma16816(acc[nb2 * 2 + 1], a0, a1, a2, a3, b2, b3);
        }
        if (s + 1 < NST) stage((s + 1) & 1);
    }

    // epilogue: D element (row, col) per PTX c-frag mapping
    int r0 = wm * 16 + (lane >> 2);
    int c0 = wn * 128 + (lane & 3) * 2;
#pragma unroll
    for (int nb = 0; nb < 16; nb++) {
        int c = c0 + nb * 8;
        *(float2*)&g_part[b][r0][c]     = make_float2(acc[nb][0], acc[nb][1]);
        *(float2*)&g_part[b][r0 + 8][c] = make_float2(acc[nb][2], acc[nb][3]);
    }
}

// reduce level 1: fold KBLK partials in RGRP groups
__global__ void reduce1_k() {
    int m   = blockIdx.x;
    int grp = blockIdx.y;
    int f   = threadIdx.x;
    int b0  = grp * RSPAN;
    int bn  = KBLK - b0; if (bn > RSPAN) bn = RSPAN;
    float a[4] = {0.f, 0.f, 0.f, 0.f};
    int q = 0;
    for (; q + 4 <= bn; q += 4) {
        a[0] += g_part[b0 + q + 0][m][f];
        a[1] += g_part[b0 + q + 1][m][f];
        a[2] += g_part[b0 + q + 2][m][f];
        a[3] += g_part[b0 + q + 3][m][f];
    }
    float acc = (a[0] + a[1]) + (a[2] + a[3]);
    for (; q < bn; q++) acc += g_part[b0 + q][m][f];
    g_r1[grp][m][f] = acc;
}

// reduce level 2: fold groups, normalize, map A-rows -> XF rows
__global__ void reduce2_k() {
    int m = blockIdx.x;
    int f = threadIdx.x;
    int g = (m < NG) ? m : (m - NG);
    int cnt = g_cnt[g];
    float inv = cnt > 0 ? 1.0f / (float)cnt : 0.0f;
    float acc = 0.f;
#pragma unroll
    for (int q = 0; q < RGRP; q++) acc += g_r1[q][m][f];
    int row = (m < NG) ? (NG + m) : (m - NG);   // dst-pool -> 64.., src-pool -> 0..
    g_XF[row][f] = acc * inv;
}

// one affine layer: P = (A @ W + b) * flag ; scatter into output
__global__ void head_k(const float* __restrict__ A, int K,
                       const float* __restrict__ W, const float* __restrict__ bias,
                       float* __restrict__ Pout, float* __restrict__ out, int layer) {
    __shared__ float As[16][17];
    __shared__ float Ws[16][17];
    int r0 = blockIdx.y * 16;
    int c0 = blockIdx.x * 16;
    int ty = threadIdx.y, tx = threadIdx.x;
    float acc = 0.f;
    for (int k0 = 0; k0 < K; k0 += 16) {
        As[ty][tx] = A[(r0 + ty) * K + k0 + tx];
        Ws[ty][tx] = W[(k0 + ty) * HID + c0 + tx];
        __syncthreads();
#pragma unroll
        for (int kk = 0; kk < 16; kk++) acc += As[ty][kk] * Ws[kk][tx];
        __syncthreads();
    }
    int r = r0 + ty, c = c0 + tx;
    int g = r & (NG - 1);
    float flag = g_cnt[g] > 0 ? 1.0f : 0.0f;
    float v = (acc + bias[c]) * flag;
    if (Pout) Pout[r * HID + c] = v;
    int col = layer * 256 + ((r < NG) ? 0 : HID) + c;
    out[g * 768 + col] = v;
}

// ---------------- launcher ----------------
extern "C" void kernel_launch(void* const* d_in, const int* in_sizes, int n_in,
                              void* d_out, int out_size) {
    const float* x     = (const float*)d_in[0];
    const int*   eidx  = (const int*)d_in[1];
    const int*   batch = (const int*)d_in[2];
    const float* W0 = (const float*)d_in[3];
    const float* b0 = (const float*)d_in[4];
    const float* W1 = (const float*)d_in[5];
    const float* b1 = (const float*)d_in[6];
    const float* W2 = (const float*)d_in[7];
    const float* b2 = (const float*)d_in[8];
    float* out = (float*)d_out;

    const int* src = eidx;
    const int* dst = eidx + NEDGES;

    zero_k<<<(NNODES * 16 / 4 + 255) / 256, 256>>>();
    count_k<<<NEDGES / 256, 256>>>(src, dst, batch);
    mm_k<<<KBLK, 512>>>(x, batch);
    reduce1_k<<<dim3(128, RGRP), IND>>>();
    reduce2_k<<<128, IND>>>();

    float *P0, *P1;
    cudaGetSymbolAddress((void**)&P0, g_P);
    P1 = P0 + 128 * HID;
    float* XF;
    cudaGetSymbolAddress((void**)&XF, g_XF);

    dim3 hb(16, 16), hg(HID / 16, 128 / 16);
    head_k<<<hg, hb>>>(XF, IND, W0, b0, P0, out, 0);
    head_k<<<hg, hb>>>(P0, HID, W1, b1, P1, out, 1);
    head_k<<<hg, hb>>>(P1, HID, W2, b2, nullptr, out, 2);
}